// round 12
// baseline (speedup 1.0000x reference)
#include <cuda_runtime.h>

// Problem constants
#define HDIM   512
#define BATCH  2
#define SEQ    128
#define DSRC   768
#define NTOK   (BATCH * SEQ)   // 256
#define NITER  30
#define BSZ    16              // sorted-block size (elements)
#define NBLK   (HDIM / BSZ)    // 32 blocks
#define NPAIR  (BSZ / 2)       // 8 packed pairs per block

// -(SCALE/REG) * log2(e) = -5000 * 1.4426950408889634
#define NEGC  (-7213.4752044448170f)
#define CPOS  (7213.4752044448170f)
// -log2(H)
#define LOGMARG2 (-9.0f)
// cutoff: drop terms with tau < -TW. Dropped mass <= 512*2^-28 ~ 1.9e-6 of
// a unit row sum per pass; accumulated over 60 passes ~1e-5 plan-relative.
#define TW 28.0f

typedef unsigned long long ull;

// Scratch (static device globals; no runtime allocation allowed)
__device__ float g_src[NTOK * HDIM];            // 512 KB
__device__ float g_sumP[BATCH * HDIM * HDIM];   // 2 MB

__device__ __forceinline__ float ex2(float x) {
    float y; asm("ex2.approx.f32 %0, %1;" : "=f"(y) : "f"(x)); return y;
}
__device__ __forceinline__ float lg2(float x) {
    float y; asm("lg2.approx.f32 %0, %1;" : "=f"(y) : "f"(x)); return y;
}
__device__ __forceinline__ ull pack2(float lo, float hi) {
    ull r; asm("mov.b64 %0, {%1, %2};" : "=l"(r) : "f"(lo), "f"(hi)); return r;
}
__device__ __forceinline__ void unpack2(ull v, float& lo, float& hi) {
    asm("mov.b64 {%0, %1}, %2;" : "=f"(lo), "=f"(hi) : "l"(v));
}
__device__ __forceinline__ ull subx2(ull a, ull b) {
    ull r; asm("sub.rn.f32x2 %0, %1, %2;" : "=l"(r) : "l"(a), "l"(b)); return r;
}
__device__ __forceinline__ ull addx2(ull a, ull b) {
    ull r; asm("add.rn.f32x2 %0, %1, %2;" : "=l"(r) : "l"(a), "l"(b)); return r;
}
__device__ __forceinline__ ull mulx2(ull a, ull b) {
    ull r; asm("mul.rn.f32x2 %0, %1, %2;" : "=l"(r) : "l"(a), "l"(b)); return r;
}
__device__ __forceinline__ ull fmax2p(ull a, ull b, ull c) {
    ull r; asm("fma.rn.f32x2 %0, %1, %2, %3;" : "=l"(r) : "l"(a), "l"(b), "l"(c)); return r;
}

// ---------------------------------------------------------------------------
// Stage 0: zero plan accumulator AND d_out (harness poisons it; out_kernel
// accumulates with atomics). Graph replays -> must run every launch.
// ---------------------------------------------------------------------------
#define NZ_P   (BATCH * HDIM * HDIM / 4)   // 131072 float4
#define NZ_OUT (NTOK * HDIM / 4)           // 32768 float4
__global__ void zero_kernel(float* __restrict__ out) {
    int i = blockIdx.x * blockDim.x + threadIdx.x;
    float4 z = make_float4(0.f, 0.f, 0.f, 0.f);
    if (i < NZ_P) reinterpret_cast<float4*>(g_sumP)[i] = z;
    else          reinterpret_cast<float4*>(out)[i - NZ_P] = z;
}

// ---------------------------------------------------------------------------
// Stage 1: src[tok, h] = X[tok] . W[h] + b[h]   (4 tokens per CTA)
// ---------------------------------------------------------------------------
#define TPG 4
__global__ void __launch_bounds__(HDIM) src_kernel(
    const float* __restrict__ X, const float* __restrict__ W,
    const float* __restrict__ b)
{
    const int tok0 = blockIdx.x * TPG;
    __shared__ __align__(16) float xs[TPG][DSRC];   // 12 KB
    for (int idx = threadIdx.x; idx < TPG * DSRC; idx += HDIM)
        xs[idx / DSRC][idx % DSRC] = X[tok0 * DSRC + idx];
    __syncthreads();

    const int h = threadIdx.x;
    const float4* wr = reinterpret_cast<const float4*>(W + (size_t)h * DSRC);
    float acc0 = 0.f, acc1 = 0.f, acc2 = 0.f, acc3 = 0.f;
#pragma unroll 4
    for (int q = 0; q < DSRC / 4; q++) {
        float4 w4 = wr[q];
        float4 x0 = reinterpret_cast<const float4*>(xs[0])[q];
        float4 x1 = reinterpret_cast<const float4*>(xs[1])[q];
        float4 x2 = reinterpret_cast<const float4*>(xs[2])[q];
        float4 x3 = reinterpret_cast<const float4*>(xs[3])[q];
        acc0 = fmaf(w4.x, x0.x, acc0); acc0 = fmaf(w4.y, x0.y, acc0);
        acc0 = fmaf(w4.z, x0.z, acc0); acc0 = fmaf(w4.w, x0.w, acc0);
        acc1 = fmaf(w4.x, x1.x, acc1); acc1 = fmaf(w4.y, x1.y, acc1);
        acc1 = fmaf(w4.z, x1.z, acc1); acc1 = fmaf(w4.w, x1.w, acc1);
        acc2 = fmaf(w4.x, x2.x, acc2); acc2 = fmaf(w4.y, x2.y, acc2);
        acc2 = fmaf(w4.z, x2.z, acc2); acc2 = fmaf(w4.w, x2.w, acc2);
        acc3 = fmaf(w4.x, x3.x, acc3); acc3 = fmaf(w4.y, x3.y, acc3);
        acc3 = fmaf(w4.z, x3.z, acc3); acc3 = fmaf(w4.w, x3.w, acc3);
    }
    float bh = b[h];
    g_src[(tok0 + 0) * HDIM + h] = acc0 + bh;
    g_src[(tok0 + 1) * HDIM + h] = acc1 + bh;
    g_src[(tok0 + 2) * HDIM + h] = acc2 + bh;
    g_src[(tok0 + 3) * HDIM + h] = acc3 + bh;
}

// ---------------------------------------------------------------------------
// Binary search over a sorted float array (u-init only).
// ---------------------------------------------------------------------------
__device__ __forceinline__ int lboundf(const float* __restrict__ A, float x) {
    int lo = 0, hi = HDIM;
    while (lo < hi) { int m = (lo + hi) >> 1; if (A[m] < x) lo = m + 1; else hi = m; }
    return lo;
}

// ---------------------------------------------------------------------------
// One culled half-pass sum with packed f32x2 math.
// Q[p] = (x_{2p}, x_{2p+1}, dual_{2p}, dual_{2p+1}) for sorted positions.
// a = sum over qualifying elements of 2^( NEGC*(x - own)^2 + dual + sh ).
// 16-element blocks (8 pairs) are skipped when even their best case
// (block max dual, closest boundary distance) stays below -TW.
// ---------------------------------------------------------------------------
__device__ __forceinline__ float culled_sum(const float4* __restrict__ Q,
                                            const float2* __restrict__ blkRange,
                                            const float* __restrict__ blkMax,
                                            float own, float sh, ull negc2)
{
    const ull own2 = pack2(own, own);
    const ull sh2  = pack2(sh, sh);
    float a0 = 1e-30f, a1 = 0.f;
#pragma unroll 1
    for (int b = 0; b < NBLK; b++) {
        float2 rg = blkRange[b];
        float dd = fmaxf(fmaxf(rg.x - own, own - rg.y), 0.0f);
        if (fmaf(dd * dd, NEGC, blkMax[b] + sh) >= -TW) {
#pragma unroll
            for (int p = NPAIR * b; p < NPAIR * b + NPAIR; p++) {
                float4 q = Q[p];
                ull X  = pack2(q.x, q.y);
                ull Yd = pack2(q.z, q.w);
                ull d  = subx2(X, own2);
                ull sq = mulx2(d, d);
                ull ys = addx2(Yd, sh2);
                ull e  = fmax2p(sq, negc2, ys);
                float el, eh; unpack2(e, el, eh);
                a0 += ex2(el);
                a1 += ex2(eh);
            }
        }
    }
    return a0 + a1;
}

// ---------------------------------------------------------------------------
// Stage 2: block-culled per-token base-2 log-domain Sinkhorn.
// s,t bitonic-sorted with index payloads; packed pair arrays for the inner
// loop (one LDS.128 per 2 elements, f32x2 arithmetic). Thread tid owns
// sorted row tid (t side, dual u) and sorted column tid (s side, dual v).
// Lanes 0-15 of warp w form block 2w, lanes 16-31 form block 2w+1; each
// half-warp publishes its block max dual via a 4-step shfl chain.
// Half-pass: own_dual -= lg2( culled_sum ) — shifted-LSE update (exact:
// shift = own_dual + 9 keeps all terms <= 0 after each normalization;
// nearest-neighbor u-init guarantees it at iteration 0 too).
// ---------------------------------------------------------------------------
__global__ void __launch_bounds__(512, 2) sinkhorn_kernel(
    const float* __restrict__ Y)
{
    const int tok  = blockIdx.x;
    const int bat  = tok >> 7;
    const int tid  = threadIdx.x;
    const int lane = tid & 31;
    const int warp = tid >> 5;
    const int myblk = tid >> 4;            // 16-element block index (0..31)

    __shared__ float sVal[HDIM], tVal[HDIM];      // sorted values
    __shared__ int   sIdx[HDIM], tIdx[HDIM];      // sorted pos -> original
    __shared__ __align__(16) float4 SQ[HDIM / 2]; // (s0,s1,v0,v1) pairs
    __shared__ __align__(16) float4 TQ[HDIM / 2]; // (t0,t1,u0,u1) pairs
    __shared__ float2 rgS[NBLK], rgT[NBLK];       // per-block (lo,hi) values
    __shared__ float blkMaxV[NBLK], blkMaxU[NBLK];

    sVal[tid] = g_src[tok * HDIM + tid];
    tVal[tid] = Y[tok * HDIM + tid];
    sIdx[tid] = tid;
    tIdx[tid] = tid;
    if (tid < NBLK) blkMaxV[tid] = 0.f;
    __syncthreads();

    // joint bitonic sort of s and t (values + index payloads)
    for (int k = 2; k <= HDIM; k <<= 1) {
        for (int j = k >> 1; j > 0; j >>= 1) {
            int ixj = tid ^ j;
            if (ixj > tid) {
                bool up = ((tid & k) == 0);
                float a = sVal[tid], b2 = sVal[ixj];
                if (up ? (a > b2) : (a < b2)) {
                    sVal[tid] = b2; sVal[ixj] = a;
                    int ti = sIdx[tid]; sIdx[tid] = sIdx[ixj]; sIdx[ixj] = ti;
                }
                float c = tVal[tid], d2 = tVal[ixj];
                if (up ? (c > d2) : (c < d2)) {
                    tVal[tid] = d2; tVal[ixj] = c;
                    int ti = tIdx[tid]; tIdx[tid] = tIdx[ixj]; tIdx[ixj] = ti;
                }
            }
            __syncthreads();
        }
    }

    // build packed pair arrays + block ranges
    if (tid < HDIM / 2) {
        SQ[tid] = make_float4(sVal[2 * tid], sVal[2 * tid + 1], 0.f, 0.f);
        TQ[tid] = make_float4(tVal[2 * tid], tVal[2 * tid + 1], 0.f, 0.f);
    }
    if (tid < NBLK) {
        rgS[tid] = make_float2(sVal[BSZ * tid], sVal[BSZ * tid + BSZ - 1]);
        rgT[tid] = make_float2(tVal[BSZ * tid], tVal[BSZ * tid + BSZ - 1]);
    }
    __syncthreads();

    const float t_own = tVal[tid];
    const float s_own = sVal[tid];
    const int   jorig = tIdx[tid];

    // init u via nearest sorted s neighbor: u = -9 + C*d_nn^2
    float u_own;
    {
        int p = lboundf(sVal, t_own);
        float dn = 3.402823466e+38f;
        if (p < HDIM) dn = fabsf(sVal[p] - t_own);
        if (p > 0)    dn = fminf(dn, fabsf(sVal[p - 1] - t_own));
        u_own = LOGMARG2 + CPOS * dn * dn;
    }
    float v_own = 0.f;

    const ull negc2 = pack2(NEGC, NEGC);
    float* SQ_s = reinterpret_cast<float*>(SQ);
    float* TQ_s = reinterpret_cast<float*>(TQ);
    const int own_slot = (tid >> 1) * 4 + 2 + (tid & 1);
    const bool is_half_leader = ((lane & 15) == 0);

    for (int it = 0; it < NITER; it++) {
        // ---- u-pass: culled sum over sorted s blocks ----
        u_own -= lg2(culled_sum(SQ, rgS, blkMaxV, t_own, u_own + 9.0f, negc2));
        TQ_s[own_slot] = u_own;
        {
            float m = u_own;                 // half-warp (16-lane) max
#pragma unroll
            for (int o = 8; o; o >>= 1)
                m = fmaxf(m, __shfl_xor_sync(0xffffffffu, m, o));
            if (is_half_leader) blkMaxU[myblk] = m;
        }
        __syncthreads();

        // ---- v-pass: culled sum over sorted t blocks ----
        v_own -= lg2(culled_sum(TQ, rgT, blkMaxU, s_own, v_own + 9.0f, negc2));
        SQ_s[own_slot] = v_own;
        {
            float m = v_own;
#pragma unroll
            for (int o = 8; o; o >>= 1)
                m = fmaxf(m, __shfl_xor_sync(0xffffffffu, m, o));
            if (is_half_leader) blkMaxV[myblk] = m;
        }
        __syncthreads();
    }

    // ---- Plan: P[jorig, iorig] = 2^(tau - 9), tau = -C d^2 + v + u + 9 ----
    {
        float* rowdst = g_sumP + (size_t)bat * HDIM * HDIM + (size_t)jorig * HDIM;
        const float sh = u_own + 9.0f;
        const ull own2 = pack2(t_own, t_own);
        const ull sh2  = pack2(sh, sh);
#pragma unroll 1
        for (int b = 0; b < NBLK; b++) {
            float2 rg = rgS[b];
            float dd = fmaxf(fmaxf(rg.x - t_own, t_own - rg.y), 0.0f);
            if (fmaf(dd * dd, NEGC, blkMaxV[b] + sh) >= -31.0f) {
#pragma unroll
                for (int p = NPAIR * b; p < NPAIR * b + NPAIR; p++) {
                    float4 q = SQ[p];
                    ull X  = pack2(q.x, q.y);
                    ull Yd = pack2(q.z, q.w);
                    ull d  = subx2(X, own2);
                    ull sq = mulx2(d, d);
                    ull ys = addx2(Yd, sh2);
                    ull e  = fmax2p(sq, negc2, ys);
                    float el, eh; unpack2(e, el, eh);
                    if (el > -31.f) atomicAdd(rowdst + sIdx[2 * p],     ex2(el - 9.0f));
                    if (eh > -31.f) atomicAdd(rowdst + sIdx[2 * p + 1], ex2(eh - 9.0f));
                }
            }
        }
    }
}

// ---------------------------------------------------------------------------
// Stage 3: out[tok, k] += sum_{h in slice} src[tok,h]*(sumP[b,h,k]*2000
//                                                      + delta[h,k])
// Grid (16 token-groups of 16, 16 h-slices of 32). 256 CTAs, 256 threads.
// ---------------------------------------------------------------------------
#define OT_TOK 16
#define OT_H   32
__global__ void __launch_bounds__(256) out_kernel(
    const float* __restrict__ delta, float* __restrict__ out)
{
    const int tok0 = blockIdx.x * OT_TOK;
    const int h0   = blockIdx.y * OT_H;
    const int bat  = tok0 >> 7;       // OT_TOK divides SEQ -> no straddle
    const int k2   = threadIdx.x;     // float2 column index (0..255)

    __shared__ float sr[OT_TOK][OT_H];   // 2 KB
    for (int idx = threadIdx.x; idx < OT_TOK * OT_H; idx += 256)
        sr[idx / OT_H][idx % OT_H] = g_src[(tok0 + idx / OT_H) * HDIM + h0 + idx % OT_H];
    __syncthreads();

    const float2* P2 = reinterpret_cast<const float2*>(
        g_sumP + (size_t)bat * HDIM * HDIM);
    const float2* D2 = reinterpret_cast<const float2*>(delta);

    float a0[OT_TOK], a1[OT_TOK];
#pragma unroll
    for (int t = 0; t < OT_TOK; t++) { a0[t] = 0.f; a1[t] = 0.f; }

#pragma unroll 4
    for (int h = 0; h < OT_H; h++) {
        float2 p = __ldg(&P2[(h0 + h) * 256 + k2]);
        float2 d = __ldg(&D2[(h0 + h) * 256 + k2]);
        float pv0 = fmaf(p.x, 2000.0f, d.x);
        float pv1 = fmaf(p.y, 2000.0f, d.y);
#pragma unroll
        for (int t = 0; t < OT_TOK; t++) {
            float s = sr[t][h];
            a0[t] = fmaf(s, pv0, a0[t]);
            a1[t] = fmaf(s, pv1, a1[t]);
        }
    }
#pragma unroll
    for (int t = 0; t < OT_TOK; t++) {
        atomicAdd(&out[(tok0 + t) * HDIM + 2 * k2],     a0[t]);
        atomicAdd(&out[(tok0 + t) * HDIM + 2 * k2 + 1], a1[t]);
    }
}

// ---------------------------------------------------------------------------
extern "C" void kernel_launch(void* const* d_in, const int* in_sizes, int n_in,
                              void* d_out, int out_size)
{
    const float* X     = (const float*)d_in[0];  // (2,128,768)
    const float* Y     = (const float*)d_in[1];  // (2,128,512)
    const float* W     = (const float*)d_in[2];  // (512,768)
    const float* b     = (const float*)d_in[3];  // (512)
    const float* delta = (const float*)d_in[4];  // (512,512)
    float* out = (float*)d_out;                  // (2,128,512)

    zero_kernel<<<(NZ_P + NZ_OUT) / 256, 256>>>(out);
    src_kernel<<<NTOK / TPG, HDIM>>>(X, W, b);
    sinkhorn_kernel<<<NTOK, 512>>>(Y);
    dim3 ogrid(NTOK / OT_TOK, HDIM / OT_H);
    out_kernel<<<ogrid, 256>>>(delta, out);
}

// round 13
// speedup vs baseline: 1.0359x; 1.0359x over previous
#include <cuda_runtime.h>

// Problem constants
#define HDIM   512
#define BATCH  2
#define SEQ    128
#define DSRC   768
#define NTOK   (BATCH * SEQ)   // 256
#define NITER  30
#define BSZ    32              // sorted-block size (elements)
#define NBLK   (HDIM / BSZ)    // 16 blocks
#define NPAIR  (BSZ / 2)       // 16 packed pairs per block
#define MINIT  8               // minimum iterations before early exit
#define RTOL   2.0e-5f         // relative dual-change tolerance

// -(SCALE/REG) * log2(e) = -5000 * 1.4426950408889634
#define NEGC  (-7213.4752044448170f)
#define CPOS  (7213.4752044448170f)
// -log2(H)
#define LOGMARG2 (-9.0f)
// cutoff: drop terms with tau < -TW (empirically rel_err-invariant 60->28)
#define TW 28.0f

typedef unsigned long long ull;

// Scratch (static device globals; no runtime allocation allowed)
__device__ float g_src[NTOK * HDIM];            // 512 KB
__device__ float g_sumP[BATCH * HDIM * HDIM];   // 2 MB

__device__ __forceinline__ float ex2(float x) {
    float y; asm("ex2.approx.f32 %0, %1;" : "=f"(y) : "f"(x)); return y;
}
__device__ __forceinline__ float lg2(float x) {
    float y; asm("lg2.approx.f32 %0, %1;" : "=f"(y) : "f"(x)); return y;
}
__device__ __forceinline__ ull pack2(float lo, float hi) {
    ull r; asm("mov.b64 %0, {%1, %2};" : "=l"(r) : "f"(lo), "f"(hi)); return r;
}
__device__ __forceinline__ void unpack2(ull v, float& lo, float& hi) {
    asm("mov.b64 {%0, %1}, %2;" : "=f"(lo), "=f"(hi) : "l"(v));
}
__device__ __forceinline__ ull subx2(ull a, ull b) {
    ull r; asm("sub.rn.f32x2 %0, %1, %2;" : "=l"(r) : "l"(a), "l"(b)); return r;
}
__device__ __forceinline__ ull addx2(ull a, ull b) {
    ull r; asm("add.rn.f32x2 %0, %1, %2;" : "=l"(r) : "l"(a), "l"(b)); return r;
}
__device__ __forceinline__ ull mulx2(ull a, ull b) {
    ull r; asm("mul.rn.f32x2 %0, %1, %2;" : "=l"(r) : "l"(a), "l"(b)); return r;
}
__device__ __forceinline__ ull fmax2p(ull a, ull b, ull c) {
    ull r; asm("fma.rn.f32x2 %0, %1, %2, %3;" : "=l"(r) : "l"(a), "l"(b), "l"(c)); return r;
}
// warp-wide f32 max via monotone-uint mapping + int redux (sm_80+)
__device__ __forceinline__ float warp_max_f32(float x) {
    unsigned b = __float_as_uint(x);
    unsigned k = (b & 0x80000000u) ? ~b : (b | 0x80000000u);
    unsigned m;
    asm("redux.sync.max.u32 %0, %1, 0xffffffff;" : "=r"(m) : "r"(k));
    unsigned r = (m & 0x80000000u) ? (m & 0x7fffffffu) : ~m;
    return __uint_as_float(r);
}

#define NZ_P   (BATCH * HDIM * HDIM / 4)   // 131072 float4
#define NZ_OUT (NTOK * HDIM / 4)           // 32768 float4

// ---------------------------------------------------------------------------
// Stage 1: zero scratch+out (graph replays), then
// src[tok, h] = X[tok] . W[h] + b[h]   (4 tokens per CTA)
// ---------------------------------------------------------------------------
#define TPG 4
__global__ void __launch_bounds__(HDIM) src_kernel(
    const float* __restrict__ X, const float* __restrict__ W,
    const float* __restrict__ b, float* __restrict__ out)
{
    // zero g_sumP and d_out (harness poisons d_out; out_kernel accumulates)
    {
        float4 z = make_float4(0.f, 0.f, 0.f, 0.f);
        int i0 = blockIdx.x * HDIM + threadIdx.x;
        const int stride = (NTOK / TPG) * HDIM;   // 32768
#pragma unroll
        for (int i = i0; i < NZ_P + NZ_OUT; i += stride) {
            if (i < NZ_P) reinterpret_cast<float4*>(g_sumP)[i] = z;
            else          reinterpret_cast<float4*>(out)[i - NZ_P] = z;
        }
    }

    const int tok0 = blockIdx.x * TPG;
    __shared__ __align__(16) float xs[TPG][DSRC];   // 12 KB
    for (int idx = threadIdx.x; idx < TPG * DSRC; idx += HDIM)
        xs[idx / DSRC][idx % DSRC] = X[tok0 * DSRC + idx];
    __syncthreads();

    const int h = threadIdx.x;
    const float4* wr = reinterpret_cast<const float4*>(W + (size_t)h * DSRC);
    float acc0 = 0.f, acc1 = 0.f, acc2 = 0.f, acc3 = 0.f;
#pragma unroll 4
    for (int q = 0; q < DSRC / 4; q++) {
        float4 w4 = wr[q];
        float4 x0 = reinterpret_cast<const float4*>(xs[0])[q];
        float4 x1 = reinterpret_cast<const float4*>(xs[1])[q];
        float4 x2 = reinterpret_cast<const float4*>(xs[2])[q];
        float4 x3 = reinterpret_cast<const float4*>(xs[3])[q];
        acc0 = fmaf(w4.x, x0.x, acc0); acc0 = fmaf(w4.y, x0.y, acc0);
        acc0 = fmaf(w4.z, x0.z, acc0); acc0 = fmaf(w4.w, x0.w, acc0);
        acc1 = fmaf(w4.x, x1.x, acc1); acc1 = fmaf(w4.y, x1.y, acc1);
        acc1 = fmaf(w4.z, x1.z, acc1); acc1 = fmaf(w4.w, x1.w, acc1);
        acc2 = fmaf(w4.x, x2.x, acc2); acc2 = fmaf(w4.y, x2.y, acc2);
        acc2 = fmaf(w4.z, x2.z, acc2); acc2 = fmaf(w4.w, x2.w, acc2);
        acc3 = fmaf(w4.x, x3.x, acc3); acc3 = fmaf(w4.y, x3.y, acc3);
        acc3 = fmaf(w4.z, x3.z, acc3); acc3 = fmaf(w4.w, x3.w, acc3);
    }
    float bh = b[h];
    g_src[(tok0 + 0) * HDIM + h] = acc0 + bh;
    g_src[(tok0 + 1) * HDIM + h] = acc1 + bh;
    g_src[(tok0 + 2) * HDIM + h] = acc2 + bh;
    g_src[(tok0 + 3) * HDIM + h] = acc3 + bh;
}

// ---------------------------------------------------------------------------
// Binary search over a sorted float array (u-init only).
// ---------------------------------------------------------------------------
__device__ __forceinline__ int lboundf(const float* __restrict__ A, float x) {
    int lo = 0, hi = HDIM;
    while (lo < hi) { int m = (lo + hi) >> 1; if (A[m] < x) lo = m + 1; else hi = m; }
    return lo;
}

// ---------------------------------------------------------------------------
// One culled half-pass sum with packed f32x2 math; warp-uniform block votes.
// Q[p] = (x_{2p}, x_{2p+1}, dual_{2p}, dual_{2p+1}) for sorted positions.
// a = sum over qualifying elements of 2^( NEGC*(x - own)^2 + dual + sh ).
// A 32-element block is processed if ANY lane's best-case term >= -TW;
// non-qualifying lanes just add sub-2^-TW mass (strictly more accurate).
// ---------------------------------------------------------------------------
__device__ __forceinline__ float culled_sum(const float4* __restrict__ Q,
                                            const float2* __restrict__ blkRange,
                                            const float* __restrict__ blkMax,
                                            float own, float sh, ull negc2)
{
    const ull own2 = pack2(own, own);
    const ull sh2  = pack2(sh, sh);
    float a0 = 1e-30f, a1 = 0.f;
#pragma unroll 1
    for (int b = 0; b < NBLK; b++) {
        float2 rg = blkRange[b];
        float dd = fmaxf(fmaxf(rg.x - own, own - rg.y), 0.0f);
        bool qual = fmaf(dd * dd, NEGC, blkMax[b] + sh) >= -TW;
        if (__any_sync(0xffffffffu, qual)) {
#pragma unroll
            for (int p = NPAIR * b; p < NPAIR * b + NPAIR; p++) {
                float4 q = Q[p];
                ull X  = pack2(q.x, q.y);
                ull Yd = pack2(q.z, q.w);
                ull d  = subx2(X, own2);
                ull sq = mulx2(d, d);
                ull ys = addx2(Yd, sh2);
                ull e  = fmax2p(sq, negc2, ys);
                float el, eh; unpack2(e, el, eh);
                a0 += ex2(el);
                a1 += ex2(eh);
            }
        }
    }
    return a0 + a1;
}

// ---------------------------------------------------------------------------
// Stage 2: block-culled per-token base-2 log-domain Sinkhorn + relative-
// tolerance early exit.
// s,t bitonic-sorted with index payloads; packed pair arrays for the inner
// loop. Thread tid owns sorted row tid (t side, dual u) and sorted column
// tid (s side, dual v). Warp w == sorted block w; publishes blkMax.
// Half-pass: own_dual -= lg2( culled_sum ) — shifted-LSE update.
// Early exit: the iteration is trajectory-independent by convergence
// (different inits produce identical results); exit when the max RELATIVE
// dual change |delta|/(1+|dual|) < RTOL — relative scaling keeps the f32
// noise floor of large (fast-converging) duals from masking convergence.
// ---------------------------------------------------------------------------
__global__ void __launch_bounds__(512, 2) sinkhorn_kernel(
    const float* __restrict__ Y)
{
    const int tok  = blockIdx.x;
    const int bat  = tok >> 7;
    const int tid  = threadIdx.x;
    const int lane = tid & 31;
    const int warp = tid >> 5;

    __shared__ float sVal[HDIM], tVal[HDIM];      // sorted values
    __shared__ int   sIdx[HDIM], tIdx[HDIM];      // sorted pos -> original
    __shared__ __align__(16) float4 SQ[HDIM / 2]; // (s0,s1,v0,v1) pairs
    __shared__ __align__(16) float4 TQ[HDIM / 2]; // (t0,t1,u0,u1) pairs
    __shared__ float2 rgS[NBLK], rgT[NBLK];       // per-block (lo,hi) values
    __shared__ float blkMaxV[NBLK], blkMaxU[NBLK];
    __shared__ float dMax[NBLK];                  // per-warp max rel change

    sVal[tid] = g_src[tok * HDIM + tid];
    tVal[tid] = Y[tok * HDIM + tid];
    sIdx[tid] = tid;
    tIdx[tid] = tid;
    if (tid < NBLK) blkMaxV[tid] = 0.f;
    __syncthreads();

    // joint bitonic sort of s and t (values + index payloads)
    for (int k = 2; k <= HDIM; k <<= 1) {
        for (int j = k >> 1; j > 0; j >>= 1) {
            int ixj = tid ^ j;
            if (ixj > tid) {
                bool up = ((tid & k) == 0);
                float a = sVal[tid], b2 = sVal[ixj];
                if (up ? (a > b2) : (a < b2)) {
                    sVal[tid] = b2; sVal[ixj] = a;
                    int ti = sIdx[tid]; sIdx[tid] = sIdx[ixj]; sIdx[ixj] = ti;
                }
                float c = tVal[tid], d2 = tVal[ixj];
                if (up ? (c > d2) : (c < d2)) {
                    tVal[tid] = d2; tVal[ixj] = c;
                    int ti = tIdx[tid]; tIdx[tid] = tIdx[ixj]; tIdx[ixj] = ti;
                }
            }
            __syncthreads();
        }
    }

    // build packed pair arrays + block ranges
    if (tid < HDIM / 2) {
        SQ[tid] = make_float4(sVal[2 * tid], sVal[2 * tid + 1], 0.f, 0.f);
        TQ[tid] = make_float4(tVal[2 * tid], tVal[2 * tid + 1], 0.f, 0.f);
    }
    if (tid < NBLK) {
        rgS[tid] = make_float2(sVal[BSZ * tid], sVal[BSZ * tid + BSZ - 1]);
        rgT[tid] = make_float2(tVal[BSZ * tid], tVal[BSZ * tid + BSZ - 1]);
    }
    __syncthreads();

    const float t_own = tVal[tid];
    const float s_own = sVal[tid];
    const int   jorig = tIdx[tid];

    // init u via nearest sorted s neighbor: u = -9 + C*d_nn^2
    float u_own;
    {
        int p = lboundf(sVal, t_own);
        float dn = 3.402823466e+38f;
        if (p < HDIM) dn = fabsf(sVal[p] - t_own);
        if (p > 0)    dn = fminf(dn, fabsf(sVal[p - 1] - t_own));
        u_own = LOGMARG2 + CPOS * dn * dn;
    }
    float v_own = 0.f;

    const ull negc2 = pack2(NEGC, NEGC);
    float* SQ_s = reinterpret_cast<float*>(SQ);
    float* TQ_s = reinterpret_cast<float*>(TQ);
    const int own_slot = (tid >> 1) * 4 + 2 + (tid & 1);

    for (int it = 0; it < NITER; it++) {
        // ---- u-pass: culled sum over sorted s blocks ----
        float du = lg2(culled_sum(SQ, rgS, blkMaxV, t_own, u_own + 9.0f, negc2));
        u_own -= du;
        TQ_s[own_slot] = u_own;
        {
            float m = warp_max_f32(u_own);
            if (lane == 0) blkMaxU[warp] = m;
        }
        __syncthreads();

        // ---- v-pass: culled sum over sorted t blocks ----
        float dv = lg2(culled_sum(TQ, rgT, blkMaxU, s_own, v_own + 9.0f, negc2));
        v_own -= dv;
        SQ_s[own_slot] = v_own;
        {
            float m = warp_max_f32(v_own);
            float dr = fmaxf(fabsf(du) / (1.0f + fabsf(u_own)),
                             fabsf(dv) / (1.0f + fabsf(v_own)));
            float dm = warp_max_f32(dr);
            if (lane == 0) { blkMaxV[warp] = m; dMax[warp] = dm; }
        }
        __syncthreads();

        // ---- convergence check (uniform across CTA) ----
        if (it >= MINIT) {
            float mx = dMax[0];
#pragma unroll
            for (int i = 1; i < NBLK; i++) mx = fmaxf(mx, dMax[i]);
            if (mx < RTOL) break;
        }
    }

    // ---- Plan: P[jorig, iorig] = 2^(tau - 9), tau = -C d^2 + v + u + 9 ----
    {
        float* rowdst = g_sumP + (size_t)bat * HDIM * HDIM + (size_t)jorig * HDIM;
        const float sh = u_own + 9.0f;
        const ull own2 = pack2(t_own, t_own);
        const ull sh2  = pack2(sh, sh);
#pragma unroll 1
        for (int b = 0; b < NBLK; b++) {
            float2 rg = rgS[b];
            float dd = fmaxf(fmaxf(rg.x - t_own, t_own - rg.y), 0.0f);
            bool qual = fmaf(dd * dd, NEGC, blkMaxV[b] + sh) >= -31.0f;
            if (__any_sync(0xffffffffu, qual)) {
#pragma unroll 4
                for (int p = NPAIR * b; p < NPAIR * b + NPAIR; p++) {
                    float4 q = SQ[p];
                    ull X  = pack2(q.x, q.y);
                    ull Yd = pack2(q.z, q.w);
                    ull d  = subx2(X, own2);
                    ull sq = mulx2(d, d);
                    ull ys = addx2(Yd, sh2);
                    ull e  = fmax2p(sq, negc2, ys);
                    float el, eh; unpack2(e, el, eh);
                    if (el > -31.f) atomicAdd(rowdst + sIdx[2 * p],     ex2(el - 9.0f));
                    if (eh > -31.f) atomicAdd(rowdst + sIdx[2 * p + 1], ex2(eh - 9.0f));
                }
            }
        }
    }
}

// ---------------------------------------------------------------------------
// Stage 3: out[tok, k] += sum_{h in slice} src[tok,h]*(sumP[b,h,k]*2000
//                                                      + delta[h,k])
// Grid (16 token-groups of 16, 16 h-slices of 32). 256 CTAs, 256 threads.
// ---------------------------------------------------------------------------
#define OT_TOK 16
#define OT_H   32
__global__ void __launch_bounds__(256) out_kernel(
    const float* __restrict__ delta, float* __restrict__ out)
{
    const int tok0 = blockIdx.x * OT_TOK;
    const int h0   = blockIdx.y * OT_H;
    const int bat  = tok0 >> 7;       // OT_TOK divides SEQ -> no straddle
    const int k2   = threadIdx.x;     // float2 column index (0..255)

    __shared__ float sr[OT_TOK][OT_H];   // 2 KB
    for (int idx = threadIdx.x; idx < OT_TOK * OT_H; idx += 256)
        sr[idx / OT_H][idx % OT_H] = g_src[(tok0 + idx / OT_H) * HDIM + h0 + idx % OT_H];
    __syncthreads();

    const float2* P2 = reinterpret_cast<const float2*>(
        g_sumP + (size_t)bat * HDIM * HDIM);
    const float2* D2 = reinterpret_cast<const float2*>(delta);

    float a0[OT_TOK], a1[OT_TOK];
#pragma unroll
    for (int t = 0; t < OT_TOK; t++) { a0[t] = 0.f; a1[t] = 0.f; }

#pragma unroll 4
    for (int h = 0; h < OT_H; h++) {
        float2 p = __ldg(&P2[(h0 + h) * 256 + k2]);
        float2 d = __ldg(&D2[(h0 + h) * 256 + k2]);
        float pv0 = fmaf(p.x, 2000.0f, d.x);
        float pv1 = fmaf(p.y, 2000.0f, d.y);
#pragma unroll
        for (int t = 0; t < OT_TOK; t++) {
            float s = sr[t][h];
            a0[t] = fmaf(s, pv0, a0[t]);
            a1[t] = fmaf(s, pv1, a1[t]);
        }
    }
#pragma unroll
    for (int t = 0; t < OT_TOK; t++) {
        atomicAdd(&out[(tok0 + t) * HDIM + 2 * k2],     a0[t]);
        atomicAdd(&out[(tok0 + t) * HDIM + 2 * k2 + 1], a1[t]);
    }
}

// ---------------------------------------------------------------------------
extern "C" void kernel_launch(void* const* d_in, const int* in_sizes, int n_in,
                              void* d_out, int out_size)
{
    const float* X     = (const float*)d_in[0];  // (2,128,768)
    const float* Y     = (const float*)d_in[1];  // (2,128,512)
    const float* W     = (const float*)d_in[2];  // (512,768)
    const float* b     = (const float*)d_in[3];  // (512)
    const float* delta = (const float*)d_in[4];  // (512,512)
    float* out = (float*)d_out;                  // (2,128,512)

    src_kernel<<<NTOK / TPG, HDIM>>>(X, W, b, out);
    sinkhorn_kernel<<<NTOK, 512>>>(Y);
    dim3 ogrid(NTOK / OT_TOK, HDIM / OT_H);
    out_kernel<<<ogrid, 256>>>(delta, out);
}

// round 14
// speedup vs baseline: 1.0709x; 1.0338x over previous
#include <cuda_runtime.h>

// Problem constants
#define HDIM   512
#define BATCH  2
#define SEQ    128
#define DSRC   768
#define NTOK   (BATCH * SEQ)   // 256
#define NITER  30
#define BSZ    32              // sorted-block size (elements)
#define NBLK   (HDIM / BSZ)    // 16 blocks
#define NPAIR  (BSZ / 2)       // 16 packed pairs per block

// -(SCALE/REG) * log2(e) = -5000 * 1.4426950408889634
#define NEGC  (-7213.4752044448170f)
#define CPOS  (7213.4752044448170f)
// -log2(H)
#define LOGMARG2 (-9.0f)
// cutoff: drop terms with tau < -TW (rel_err empirically invariant 60->28;
// 24 drops <= 512*2^-24 ~ 3e-5 of a unit row sum)
#define TW 24.0f

typedef unsigned long long ull;

// Scratch (static device globals; no runtime allocation allowed)
__device__ float g_src[NTOK * HDIM];            // 512 KB
__device__ float g_sumP[BATCH * HDIM * HDIM];   // 2 MB

__device__ __forceinline__ float ex2(float x) {
    float y; asm("ex2.approx.f32 %0, %1;" : "=f"(y) : "f"(x)); return y;
}
__device__ __forceinline__ float lg2(float x) {
    float y; asm("lg2.approx.f32 %0, %1;" : "=f"(y) : "f"(x)); return y;
}
__device__ __forceinline__ ull pack2(float lo, float hi) {
    ull r; asm("mov.b64 %0, {%1, %2};" : "=l"(r) : "f"(lo), "f"(hi)); return r;
}
__device__ __forceinline__ void unpack2(ull v, float& lo, float& hi) {
    asm("mov.b64 {%0, %1}, %2;" : "=f"(lo), "=f"(hi) : "l"(v));
}
__device__ __forceinline__ ull subx2(ull a, ull b) {
    ull r; asm("sub.rn.f32x2 %0, %1, %2;" : "=l"(r) : "l"(a), "l"(b)); return r;
}
__device__ __forceinline__ ull addx2(ull a, ull b) {
    ull r; asm("add.rn.f32x2 %0, %1, %2;" : "=l"(r) : "l"(a), "l"(b)); return r;
}
__device__ __forceinline__ ull mulx2(ull a, ull b) {
    ull r; asm("mul.rn.f32x2 %0, %1, %2;" : "=l"(r) : "l"(a), "l"(b)); return r;
}
__device__ __forceinline__ ull fmax2p(ull a, ull b, ull c) {
    ull r; asm("fma.rn.f32x2 %0, %1, %2, %3;" : "=l"(r) : "l"(a), "l"(b), "l"(c)); return r;
}
// warp-wide f32 max via monotone-uint mapping + int redux (sm_80+)
__device__ __forceinline__ float warp_max_f32(float x) {
    unsigned b = __float_as_uint(x);
    unsigned k = (b & 0x80000000u) ? ~b : (b | 0x80000000u);
    unsigned m;
    asm("redux.sync.max.u32 %0, %1, 0xffffffff;" : "=r"(m) : "r"(k));
    unsigned r = (m & 0x80000000u) ? (m & 0x7fffffffu) : ~m;
    return __uint_as_float(r);
}

#define NZ_P   (BATCH * HDIM * HDIM / 4)   // 131072 float4
#define NZ_OUT (NTOK * HDIM / 4)           // 32768 float4

// ---------------------------------------------------------------------------
// Stage 1: zero scratch+out (graph replays), then
// src[tok, h] = X[tok] . W[h] + b[h]   (2 tokens per CTA, 128 CTAs:
// full-SM coverage + short per-thread load chains; W L2 traffic 192 MB)
// ---------------------------------------------------------------------------
#define TPG 2
__global__ void __launch_bounds__(HDIM) src_kernel(
    const float* __restrict__ X, const float* __restrict__ W,
    const float* __restrict__ b, float* __restrict__ out)
{
    // zero g_sumP and d_out (harness poisons d_out; out_kernel accumulates)
    {
        float4 z = make_float4(0.f, 0.f, 0.f, 0.f);
        int i0 = blockIdx.x * HDIM + threadIdx.x;
        const int stride = (NTOK / TPG) * HDIM;   // 65536
#pragma unroll
        for (int i = i0; i < NZ_P + NZ_OUT; i += stride) {
            if (i < NZ_P) reinterpret_cast<float4*>(g_sumP)[i] = z;
            else          reinterpret_cast<float4*>(out)[i - NZ_P] = z;
        }
    }

    const int tok0 = blockIdx.x * TPG;
    __shared__ __align__(16) float xs[TPG][DSRC];   // 6 KB
    for (int idx = threadIdx.x; idx < TPG * DSRC; idx += HDIM)
        xs[idx / DSRC][idx % DSRC] = X[tok0 * DSRC + idx];
    __syncthreads();

    const int h = threadIdx.x;
    const float4* wr = reinterpret_cast<const float4*>(W + (size_t)h * DSRC);
    float acc0 = 0.f, acc1 = 0.f;
#pragma unroll 8
    for (int q = 0; q < DSRC / 4; q++) {
        float4 w4 = wr[q];
        float4 x0 = reinterpret_cast<const float4*>(xs[0])[q];
        float4 x1 = reinterpret_cast<const float4*>(xs[1])[q];
        acc0 = fmaf(w4.x, x0.x, acc0); acc0 = fmaf(w4.y, x0.y, acc0);
        acc0 = fmaf(w4.z, x0.z, acc0); acc0 = fmaf(w4.w, x0.w, acc0);
        acc1 = fmaf(w4.x, x1.x, acc1); acc1 = fmaf(w4.y, x1.y, acc1);
        acc1 = fmaf(w4.z, x1.z, acc1); acc1 = fmaf(w4.w, x1.w, acc1);
    }
    float bh = b[h];
    g_src[(tok0 + 0) * HDIM + h] = acc0 + bh;
    g_src[(tok0 + 1) * HDIM + h] = acc1 + bh;
}

// ---------------------------------------------------------------------------
// Binary search over a sorted float array (u-init only).
// ---------------------------------------------------------------------------
__device__ __forceinline__ int lboundf(const float* __restrict__ A, float x) {
    int lo = 0, hi = HDIM;
    while (lo < hi) { int m = (lo + hi) >> 1; if (A[m] < x) lo = m + 1; else hi = m; }
    return lo;
}

// ---------------------------------------------------------------------------
// One culled half-pass sum with packed f32x2 math; warp-uniform block votes.
// Q[p] = (x_{2p}, x_{2p+1}, dual_{2p}, dual_{2p+1}) for sorted positions.
// a = sum over qualifying elements of 2^( NEGC*(x - own)^2 + dual + sh ).
// A 32-element block is processed if ANY lane's best-case term >= -TW;
// non-qualifying lanes just add sub-2^-TW mass (strictly more accurate).
// ---------------------------------------------------------------------------
__device__ __forceinline__ float culled_sum(const float4* __restrict__ Q,
                                            const float2* __restrict__ blkRange,
                                            const float* __restrict__ blkMax,
                                            float own, float sh, ull negc2)
{
    const ull own2 = pack2(own, own);
    const ull sh2  = pack2(sh, sh);
    float a0 = 1e-30f, a1 = 0.f;
#pragma unroll 1
    for (int b = 0; b < NBLK; b++) {
        float2 rg = blkRange[b];
        float dd = fmaxf(fmaxf(rg.x - own, own - rg.y), 0.0f);
        bool qual = fmaf(dd * dd, NEGC, blkMax[b] + sh) >= -TW;
        if (__any_sync(0xffffffffu, qual)) {
#pragma unroll
            for (int p = NPAIR * b; p < NPAIR * b + NPAIR; p++) {
                float4 q = Q[p];
                ull X  = pack2(q.x, q.y);
                ull Yd = pack2(q.z, q.w);
                ull d  = subx2(X, own2);
                ull sq = mulx2(d, d);
                ull ys = addx2(Yd, sh2);
                ull e  = fmax2p(sq, negc2, ys);
                float el, eh; unpack2(e, el, eh);
                a0 += ex2(el);
                a1 += ex2(eh);
            }
        }
    }
    return a0 + a1;
}

// ---------------------------------------------------------------------------
// Stage 2: block-culled per-token base-2 log-domain Sinkhorn (fixed 30
// iterations — the reference's result is NOT a converged fixed point, so
// the full trajectory must be run; early-exit experiments confirmed this).
// s,t bitonic-sorted with index payloads; packed pair arrays for the inner
// loop. Thread tid owns sorted row tid (t side, dual u) and sorted column
// tid (s side, dual v). Warp w == sorted block w; publishes blkMax.
// Half-pass: own_dual -= lg2( culled_sum ) — shifted-LSE update (exact:
// shift = own_dual + 9 keeps all terms <= 0 after each normalization;
// nearest-neighbor u-init guarantees it at iteration 0 too).
// ---------------------------------------------------------------------------
__global__ void __launch_bounds__(512, 2) sinkhorn_kernel(
    const float* __restrict__ Y)
{
    const int tok  = blockIdx.x;
    const int bat  = tok >> 7;
    const int tid  = threadIdx.x;
    const int lane = tid & 31;
    const int warp = tid >> 5;

    __shared__ float sVal[HDIM], tVal[HDIM];      // sorted values
    __shared__ int   sIdx[HDIM], tIdx[HDIM];      // sorted pos -> original
    __shared__ __align__(16) float4 SQ[HDIM / 2]; // (s0,s1,v0,v1) pairs
    __shared__ __align__(16) float4 TQ[HDIM / 2]; // (t0,t1,u0,u1) pairs
    __shared__ float2 rgS[NBLK], rgT[NBLK];       // per-block (lo,hi) values
    __shared__ float blkMaxV[NBLK], blkMaxU[NBLK];

    sVal[tid] = g_src[tok * HDIM + tid];
    tVal[tid] = Y[tok * HDIM + tid];
    sIdx[tid] = tid;
    tIdx[tid] = tid;
    if (tid < NBLK) blkMaxV[tid] = 0.f;
    __syncthreads();

    // joint bitonic sort of s and t (values + index payloads)
    for (int k = 2; k <= HDIM; k <<= 1) {
        for (int j = k >> 1; j > 0; j >>= 1) {
            int ixj = tid ^ j;
            if (ixj > tid) {
                bool up = ((tid & k) == 0);
                float a = sVal[tid], b2 = sVal[ixj];
                if (up ? (a > b2) : (a < b2)) {
                    sVal[tid] = b2; sVal[ixj] = a;
                    int ti = sIdx[tid]; sIdx[tid] = sIdx[ixj]; sIdx[ixj] = ti;
                }
                float c = tVal[tid], d2 = tVal[ixj];
                if (up ? (c > d2) : (c < d2)) {
                    tVal[tid] = d2; tVal[ixj] = c;
                    int ti = tIdx[tid]; tIdx[tid] = tIdx[ixj]; tIdx[ixj] = ti;
                }
            }
            __syncthreads();
        }
    }

    // build packed pair arrays + block ranges
    if (tid < HDIM / 2) {
        SQ[tid] = make_float4(sVal[2 * tid], sVal[2 * tid + 1], 0.f, 0.f);
        TQ[tid] = make_float4(tVal[2 * tid], tVal[2 * tid + 1], 0.f, 0.f);
    }
    if (tid < NBLK) {
        rgS[tid] = make_float2(sVal[BSZ * tid], sVal[BSZ * tid + BSZ - 1]);
        rgT[tid] = make_float2(tVal[BSZ * tid], tVal[BSZ * tid + BSZ - 1]);
    }
    __syncthreads();

    const float t_own = tVal[tid];
    const float s_own = sVal[tid];
    const int   jorig = tIdx[tid];

    // init u via nearest sorted s neighbor: u = -9 + C*d_nn^2
    float u_own;
    {
        int p = lboundf(sVal, t_own);
        float dn = 3.402823466e+38f;
        if (p < HDIM) dn = fabsf(sVal[p] - t_own);
        if (p > 0)    dn = fminf(dn, fabsf(sVal[p - 1] - t_own));
        u_own = LOGMARG2 + CPOS * dn * dn;
    }
    float v_own = 0.f;

    const ull negc2 = pack2(NEGC, NEGC);
    float* SQ_s = reinterpret_cast<float*>(SQ);
    float* TQ_s = reinterpret_cast<float*>(TQ);
    const int own_slot = (tid >> 1) * 4 + 2 + (tid & 1);

    for (int it = 0; it < NITER; it++) {
        // ---- u-pass: culled sum over sorted s blocks ----
        u_own -= lg2(culled_sum(SQ, rgS, blkMaxV, t_own, u_own + 9.0f, negc2));
        TQ_s[own_slot] = u_own;
        {
            float m = warp_max_f32(u_own);
            if (lane == 0) blkMaxU[warp] = m;
        }
        __syncthreads();

        // ---- v-pass: culled sum over sorted t blocks ----
        v_own -= lg2(culled_sum(TQ, rgT, blkMaxU, s_own, v_own + 9.0f, negc2));
        SQ_s[own_slot] = v_own;
        {
            float m = warp_max_f32(v_own);
            if (lane == 0) blkMaxV[warp] = m;
        }
        __syncthreads();
    }

    // ---- Plan: P[jorig, iorig] = 2^(tau - 9), tau = -C d^2 + v + u + 9 ----
    {
        float* rowdst = g_sumP + (size_t)bat * HDIM * HDIM + (size_t)jorig * HDIM;
        const float sh = u_own + 9.0f;
        const ull own2 = pack2(t_own, t_own);
        const ull sh2  = pack2(sh, sh);
#pragma unroll 1
        for (int b = 0; b < NBLK; b++) {
            float2 rg = rgS[b];
            float dd = fmaxf(fmaxf(rg.x - t_own, t_own - rg.y), 0.0f);
            bool qual = fmaf(dd * dd, NEGC, blkMaxV[b] + sh) >= -31.0f;
            if (__any_sync(0xffffffffu, qual)) {
#pragma unroll 4
                for (int p = NPAIR * b; p < NPAIR * b + NPAIR; p++) {
                    float4 q = SQ[p];
                    ull X  = pack2(q.x, q.y);
                    ull Yd = pack2(q.z, q.w);
                    ull d  = subx2(X, own2);
                    ull sq = mulx2(d, d);
                    ull ys = addx2(Yd, sh2);
                    ull e  = fmax2p(sq, negc2, ys);
                    float el, eh; unpack2(e, el, eh);
                    if (el > -31.f) atomicAdd(rowdst + sIdx[2 * p],     ex2(el - 9.0f));
                    if (eh > -31.f) atomicAdd(rowdst + sIdx[2 * p + 1], ex2(eh - 9.0f));
                }
            }
        }
    }
}

// ---------------------------------------------------------------------------
// Stage 3: out[tok, k] += sum_{h in slice} src[tok,h]*(sumP[b,h,k]*2000
//                                                      + delta[h,k])
// Grid (16 token-groups of 16, 16 h-slices of 32). 256 CTAs, 256 threads.
// ---------------------------------------------------------------------------
#define OT_TOK 16
#define OT_H   32
__global__ void __launch_bounds__(256) out_kernel(
    const float* __restrict__ delta, float* __restrict__ out)
{
    const int tok0 = blockIdx.x * OT_TOK;
    const int h0   = blockIdx.y * OT_H;
    const int bat  = tok0 >> 7;       // OT_TOK divides SEQ -> no straddle
    const int k2   = threadIdx.x;     // float2 column index (0..255)

    __shared__ float sr[OT_TOK][OT_H];   // 2 KB
    for (int idx = threadIdx.x; idx < OT_TOK * OT_H; idx += 256)
        sr[idx / OT_H][idx % OT_H] = g_src[(tok0 + idx / OT_H) * HDIM + h0 + idx % OT_H];
    __syncthreads();

    const float2* P2 = reinterpret_cast<const float2*>(
        g_sumP + (size_t)bat * HDIM * HDIM);
    const float2* D2 = reinterpret_cast<const float2*>(delta);

    float a0[OT_TOK], a1[OT_TOK];
#pragma unroll
    for (int t = 0; t < OT_TOK; t++) { a0[t] = 0.f; a1[t] = 0.f; }

#pragma unroll 4
    for (int h = 0; h < OT_H; h++) {
        float2 p = __ldg(&P2[(h0 + h) * 256 + k2]);
        float2 d = __ldg(&D2[(h0 + h) * 256 + k2]);
        float pv0 = fmaf(p.x, 2000.0f, d.x);
        float pv1 = fmaf(p.y, 2000.0f, d.y);
#pragma unroll
        for (int t = 0; t < OT_TOK; t++) {
            float s = sr[t][h];
            a0[t] = fmaf(s, pv0, a0[t]);
            a1[t] = fmaf(s, pv1, a1[t]);
        }
    }
#pragma unroll
    for (int t = 0; t < OT_TOK; t++) {
        atomicAdd(&out[(tok0 + t) * HDIM + 2 * k2],     a0[t]);
        atomicAdd(&out[(tok0 + t) * HDIM + 2 * k2 + 1], a1[t]);
    }
}

// ---------------------------------------------------------------------------
extern "C" void kernel_launch(void* const* d_in, const int* in_sizes, int n_in,
                              void* d_out, int out_size)
{
    const float* X     = (const float*)d_in[0];  // (2,128,768)
    const float* Y     = (const float*)d_in[1];  // (2,128,512)
    const float* W     = (const float*)d_in[2];  // (512,768)
    const float* b     = (const float*)d_in[3];  // (512)
    const float* delta = (const float*)d_in[4];  // (512,512)
    float* out = (float*)d_out;                  // (2,128,512)

    src_kernel<<<NTOK / TPG, HDIM>>>(X, W, b, out);
    sinkhorn_kernel<<<NTOK, 512>>>(Y);
    dim3 ogrid(NTOK / OT_TOK, HDIM / OT_H);
    out_kernel<<<ogrid, 256>>>(delta, out);
}

// round 15
// speedup vs baseline: 1.1356x; 1.0604x over previous
#include <cuda_runtime.h>

// Problem constants
#define HDIM   512
#define BATCH  2
#define SEQ    128
#define DSRC   768
#define NTOK   (BATCH * SEQ)   // 256
#define NITER  30
#define BSZ    32              // sorted-block size (elements)
#define NBLK   (HDIM / BSZ)    // 16 blocks
#define NPAIR  (BSZ / 2)       // 16 packed pairs per block

// -(SCALE/REG) * log2(e) = -5000 * 1.4426950408889634
#define NEGC  (-7213.4752044448170f)
#define CPOS  (7213.4752044448170f)
// -log2(H)
#define LOGMARG2 (-9.0f)
// cutoff: drop terms with tau < -TW (rel_err empirically invariant 60->24)
#define TW 24.0f

typedef unsigned long long ull;

// Scratch (static device globals; no runtime allocation allowed)
__device__ float g_src[NTOK * HDIM];            // 512 KB
__device__ float g_sumP[BATCH * HDIM * HDIM];   // 2 MB

__device__ __forceinline__ float ex2(float x) {
    float y; asm("ex2.approx.f32 %0, %1;" : "=f"(y) : "f"(x)); return y;
}
__device__ __forceinline__ float lg2(float x) {
    float y; asm("lg2.approx.f32 %0, %1;" : "=f"(y) : "f"(x)); return y;
}
__device__ __forceinline__ ull pack2(float lo, float hi) {
    ull r; asm("mov.b64 %0, {%1, %2};" : "=l"(r) : "f"(lo), "f"(hi)); return r;
}
__device__ __forceinline__ void unpack2(ull v, float& lo, float& hi) {
    asm("mov.b64 {%0, %1}, %2;" : "=f"(lo), "=f"(hi) : "l"(v));
}
__device__ __forceinline__ ull subx2(ull a, ull b) {
    ull r; asm("sub.rn.f32x2 %0, %1, %2;" : "=l"(r) : "l"(a), "l"(b)); return r;
}
__device__ __forceinline__ ull addx2(ull a, ull b) {
    ull r; asm("add.rn.f32x2 %0, %1, %2;" : "=l"(r) : "l"(a), "l"(b)); return r;
}
__device__ __forceinline__ ull mulx2(ull a, ull b) {
    ull r; asm("mul.rn.f32x2 %0, %1, %2;" : "=l"(r) : "l"(a), "l"(b)); return r;
}
__device__ __forceinline__ ull fmax2p(ull a, ull b, ull c) {
    ull r; asm("fma.rn.f32x2 %0, %1, %2, %3;" : "=l"(r) : "l"(a), "l"(b), "l"(c)); return r;
}
// warp-wide f32 max via monotone-uint mapping + int redux (sm_80+)
__device__ __forceinline__ float warp_max_f32(float x) {
    unsigned b = __float_as_uint(x);
    unsigned k = (b & 0x80000000u) ? ~b : (b | 0x80000000u);
    unsigned m;
    asm("redux.sync.max.u32 %0, %1, 0xffffffff;" : "=r"(m) : "r"(k));
    unsigned r = (m & 0x80000000u) ? (m & 0x7fffffffu) : ~m;
    return __uint_as_float(r);
}

#define NZ_P   (BATCH * HDIM * HDIM / 4)   // 131072 float4
#define NZ_OUT (NTOK * HDIM / 4)           // 32768 float4

// ---------------------------------------------------------------------------
// Stage 1: zero scratch+out (graph replays), then tiled GEMM
// src[tok, h] = X[tok] . W[h] + b[h].
// CTA tile: 8 tokens x 128 h, K chunked by 64. W tile transposed into smem
// [k][h] once and reused by all 8 tokens -> W L1/L2 traffic 48 MB (vs 192).
// Thread owns 4 h x 1 token: per k one LDS.128 (w) + broadcast LDS (x) + 4 FMA.
// ---------------------------------------------------------------------------
#define BT    8      // tokens per CTA tile
#define BH    128    // h per CTA tile
#define KC    64     // k-chunk
#define WPAD  132    // Ws row stride in floats (128 + 4: LDS.128 phase-clean)
#define XPAD  9      // Xs row stride in floats (odd: conflict-free writes)
__global__ void __launch_bounds__(256, 2) src_kernel(
    const float* __restrict__ X, const float* __restrict__ W,
    const float* __restrict__ b, float* __restrict__ out)
{
    const int tid = threadIdx.x;
    // zero g_sumP and d_out (harness poisons d_out; out_kernel accumulates)
    {
        float4 z = make_float4(0.f, 0.f, 0.f, 0.f);
        int cta = blockIdx.y * gridDim.x + blockIdx.x;       // 0..127
        int i0 = cta * 256 + tid;
        const int stride = 128 * 256;                         // 32768
#pragma unroll
        for (int i = i0; i < NZ_P + NZ_OUT; i += stride) {
            if (i < NZ_P) reinterpret_cast<float4*>(g_sumP)[i] = z;
            else          reinterpret_cast<float4*>(out)[i - NZ_P] = z;
        }
    }

    const int tok0 = blockIdx.x * BT;    // gridDim.x = 32
    const int h0   = blockIdx.y * BH;    // gridDim.y = 4

    __shared__ __align__(16) float Ws[KC * WPAD];   // 33 KB, [kk][h]
    __shared__ float Xs[KC * XPAD];                 // 2.25 KB, [kk][tok]

    const int hq = (tid & 31) * 4;   // 4-h group within tile (0..124)
    const int tk = tid >> 5;         // token within tile (0..7)
    float acc0 = 0.f, acc1 = 0.f, acc2 = 0.f, acc3 = 0.f;

    for (int k0 = 0; k0 < DSRC; k0 += KC) {
        __syncthreads();   // protect previous chunk's reads
        // load X tile: 8 tok x 64 k = 512 floats, 2 per thread (coalesced)
        {
            int idx = tid;
#pragma unroll
            for (int r = 0; r < 2; r++, idx += 256) {
                int tt = idx >> 6;         // token 0..7
                int kk = idx & 63;
                Xs[kk * XPAD + tt] = X[(tok0 + tt) * DSRC + k0 + kk];
            }
        }
        // load+transpose W tile: thread t -> h = t/2, k-half = (t&1)*32
        {
            int h  = tid >> 1;
            int kb = (tid & 1) * 32;
            const float4* wsrc = reinterpret_cast<const float4*>(
                W + (size_t)(h0 + h) * DSRC + k0 + kb);
#pragma unroll
            for (int j = 0; j < 8; j++) {
                float4 w4 = wsrc[j];
                int kk = kb + j * 4;
                Ws[(kk + 0) * WPAD + h] = w4.x;
                Ws[(kk + 1) * WPAD + h] = w4.y;
                Ws[(kk + 2) * WPAD + h] = w4.z;
                Ws[(kk + 3) * WPAD + h] = w4.w;
            }
        }
        __syncthreads();
        // compute: per kk one LDS.128 of w + broadcast x + 4 FMA
#pragma unroll 8
        for (int kk = 0; kk < KC; kk++) {
            float4 w = *reinterpret_cast<const float4*>(&Ws[kk * WPAD + hq]);
            float x = Xs[kk * XPAD + tk];
            acc0 = fmaf(w.x, x, acc0);
            acc1 = fmaf(w.y, x, acc1);
            acc2 = fmaf(w.z, x, acc2);
            acc3 = fmaf(w.w, x, acc3);
        }
    }

    float4 bb = *reinterpret_cast<const float4*>(&b[h0 + hq]);
    float4 res = make_float4(acc0 + bb.x, acc1 + bb.y, acc2 + bb.z, acc3 + bb.w);
    *reinterpret_cast<float4*>(&g_src[(tok0 + tk) * HDIM + h0 + hq]) = res;
}

// ---------------------------------------------------------------------------
// Binary search over a sorted float array (u-init only).
// ---------------------------------------------------------------------------
__device__ __forceinline__ int lboundf(const float* __restrict__ A, float x) {
    int lo = 0, hi = HDIM;
    while (lo < hi) { int m = (lo + hi) >> 1; if (A[m] < x) lo = m + 1; else hi = m; }
    return lo;
}

// ---------------------------------------------------------------------------
// One culled half-pass sum with packed f32x2 math; warp-uniform block votes.
// Q[p] = (x_{2p}, x_{2p+1}, dual_{2p}, dual_{2p+1}) for sorted positions.
// a = sum over qualifying elements of 2^( NEGC*(x - own)^2 + dual + sh ).
// A 32-element block is processed if ANY lane's best-case term >= -TW;
// non-qualifying lanes just add sub-2^-TW mass (strictly more accurate).
// ---------------------------------------------------------------------------
__device__ __forceinline__ float culled_sum(const float4* __restrict__ Q,
                                            const float2* __restrict__ blkRange,
                                            const float* __restrict__ blkMax,
                                            float own, float sh, ull negc2)
{
    const ull own2 = pack2(own, own);
    const ull sh2  = pack2(sh, sh);
    float a0 = 1e-30f, a1 = 0.f;
#pragma unroll 1
    for (int b = 0; b < NBLK; b++) {
        float2 rg = blkRange[b];
        float dd = fmaxf(fmaxf(rg.x - own, own - rg.y), 0.0f);
        bool qual = fmaf(dd * dd, NEGC, blkMax[b] + sh) >= -TW;
        if (__any_sync(0xffffffffu, qual)) {
#pragma unroll
            for (int p = NPAIR * b; p < NPAIR * b + NPAIR; p++) {
                float4 q = Q[p];
                ull X  = pack2(q.x, q.y);
                ull Yd = pack2(q.z, q.w);
                ull d  = subx2(X, own2);
                ull sq = mulx2(d, d);
                ull ys = addx2(Yd, sh2);
                ull e  = fmax2p(sq, negc2, ys);
                float el, eh; unpack2(e, el, eh);
                a0 += ex2(el);
                a1 += ex2(eh);
            }
        }
    }
    return a0 + a1;
}

// ---------------------------------------------------------------------------
// Stage 2: block-culled per-token base-2 log-domain Sinkhorn (fixed 30
// iterations — the reference's result is NOT a converged fixed point).
// s,t bitonic-sorted with index payloads; packed pair arrays for the inner
// loop. Thread tid owns sorted row tid (t side, dual u) and sorted column
// tid (s side, dual v). Warp w == sorted block w; publishes blkMax.
// Half-pass: own_dual -= lg2( culled_sum ) — shifted-LSE update (exact:
// shift = own_dual + 9 keeps all terms <= 0 after each normalization;
// nearest-neighbor u-init guarantees it at iteration 0 too).
// ---------------------------------------------------------------------------
__global__ void __launch_bounds__(512, 2) sinkhorn_kernel(
    const float* __restrict__ Y)
{
    const int tok  = blockIdx.x;
    const int bat  = tok >> 7;
    const int tid  = threadIdx.x;
    const int lane = tid & 31;
    const int warp = tid >> 5;

    __shared__ float sVal[HDIM], tVal[HDIM];      // sorted values
    __shared__ int   sIdx[HDIM], tIdx[HDIM];      // sorted pos -> original
    __shared__ __align__(16) float4 SQ[HDIM / 2]; // (s0,s1,v0,v1) pairs
    __shared__ __align__(16) float4 TQ[HDIM / 2]; // (t0,t1,u0,u1) pairs
    __shared__ float2 rgS[NBLK], rgT[NBLK];       // per-block (lo,hi) values
    __shared__ float blkMaxV[NBLK], blkMaxU[NBLK];

    sVal[tid] = g_src[tok * HDIM + tid];
    tVal[tid] = Y[tok * HDIM + tid];
    sIdx[tid] = tid;
    tIdx[tid] = tid;
    if (tid < NBLK) blkMaxV[tid] = 0.f;
    __syncthreads();

    // joint bitonic sort of s and t (values + index payloads)
    for (int k = 2; k <= HDIM; k <<= 1) {
        for (int j = k >> 1; j > 0; j >>= 1) {
            int ixj = tid ^ j;
            if (ixj > tid) {
                bool up = ((tid & k) == 0);
                float a = sVal[tid], b2 = sVal[ixj];
                if (up ? (a > b2) : (a < b2)) {
                    sVal[tid] = b2; sVal[ixj] = a;
                    int ti = sIdx[tid]; sIdx[tid] = sIdx[ixj]; sIdx[ixj] = ti;
                }
                float c = tVal[tid], d2 = tVal[ixj];
                if (up ? (c > d2) : (c < d2)) {
                    tVal[tid] = d2; tVal[ixj] = c;
                    int ti = tIdx[tid]; tIdx[tid] = tIdx[ixj]; tIdx[ixj] = ti;
                }
            }
            __syncthreads();
        }
    }

    // build packed pair arrays + block ranges
    if (tid < HDIM / 2) {
        SQ[tid] = make_float4(sVal[2 * tid], sVal[2 * tid + 1], 0.f, 0.f);
        TQ[tid] = make_float4(tVal[2 * tid], tVal[2 * tid + 1], 0.f, 0.f);
    }
    if (tid < NBLK) {
        rgS[tid] = make_float2(sVal[BSZ * tid], sVal[BSZ * tid + BSZ - 1]);
        rgT[tid] = make_float2(tVal[BSZ * tid], tVal[BSZ * tid + BSZ - 1]);
    }
    __syncthreads();

    const float t_own = tVal[tid];
    const float s_own = sVal[tid];
    const int   jorig = tIdx[tid];

    // init u via nearest sorted s neighbor: u = -9 + C*d_nn^2
    float u_own;
    {
        int p = lboundf(sVal, t_own);
        float dn = 3.402823466e+38f;
        if (p < HDIM) dn = fabsf(sVal[p] - t_own);
        if (p > 0)    dn = fminf(dn, fabsf(sVal[p - 1] - t_own));
        u_own = LOGMARG2 + CPOS * dn * dn;
    }
    float v_own = 0.f;

    const ull negc2 = pack2(NEGC, NEGC);
    float* SQ_s = reinterpret_cast<float*>(SQ);
    float* TQ_s = reinterpret_cast<float*>(TQ);
    const int own_slot = (tid >> 1) * 4 + 2 + (tid & 1);

    for (int it = 0; it < NITER; it++) {
        // ---- u-pass: culled sum over sorted s blocks ----
        u_own -= lg2(culled_sum(SQ, rgS, blkMaxV, t_own, u_own + 9.0f, negc2));
        TQ_s[own_slot] = u_own;
        {
            float m = warp_max_f32(u_own);
            if (lane == 0) blkMaxU[warp] = m;
        }
        __syncthreads();

        // ---- v-pass: culled sum over sorted t blocks ----
        v_own -= lg2(culled_sum(TQ, rgT, blkMaxU, s_own, v_own + 9.0f, negc2));
        SQ_s[own_slot] = v_own;
        {
            float m = warp_max_f32(v_own);
            if (lane == 0) blkMaxV[warp] = m;
        }
        __syncthreads();
    }

    // ---- Plan: P[jorig, iorig] = 2^(tau - 9), tau = -C d^2 + v + u + 9 ----
    {
        float* rowdst = g_sumP + (size_t)bat * HDIM * HDIM + (size_t)jorig * HDIM;
        const float sh = u_own + 9.0f;
        const ull own2 = pack2(t_own, t_own);
        const ull sh2  = pack2(sh, sh);
#pragma unroll 1
        for (int b = 0; b < NBLK; b++) {
            float2 rg = rgS[b];
            float dd = fmaxf(fmaxf(rg.x - t_own, t_own - rg.y), 0.0f);
            bool qual = fmaf(dd * dd, NEGC, blkMaxV[b] + sh) >= -31.0f;
            if (__any_sync(0xffffffffu, qual)) {
#pragma unroll 4
                for (int p = NPAIR * b; p < NPAIR * b + NPAIR; p++) {
                    float4 q = SQ[p];
                    ull X  = pack2(q.x, q.y);
                    ull Yd = pack2(q.z, q.w);
                    ull d  = subx2(X, own2);
                    ull sq = mulx2(d, d);
                    ull ys = addx2(Yd, sh2);
                    ull e  = fmax2p(sq, negc2, ys);
                    float el, eh; unpack2(e, el, eh);
                    if (el > -31.f) atomicAdd(rowdst + sIdx[2 * p],     ex2(el - 9.0f));
                    if (eh > -31.f) atomicAdd(rowdst + sIdx[2 * p + 1], ex2(eh - 9.0f));
                }
            }
        }
    }
}

// ---------------------------------------------------------------------------
// Stage 3: out[tok, k] += sum_{h in slice} src[tok,h]*(sumP[b,h,k]*2000
//                                                      + delta[h,k])
// Grid (16 token-groups of 16, 16 h-slices of 32). 256 CTAs, 256 threads.
// ---------------------------------------------------------------------------
#define OT_TOK 16
#define OT_H   32
__global__ void __launch_bounds__(256) out_kernel(
    const float* __restrict__ delta, float* __restrict__ out)
{
    const int tok0 = blockIdx.x * OT_TOK;
    const int h0   = blockIdx.y * OT_H;
    const int bat  = tok0 >> 7;       // OT_TOK divides SEQ -> no straddle
    const int k2   = threadIdx.x;     // float2 column index (0..255)

    __shared__ float sr[OT_TOK][OT_H];   // 2 KB
    for (int idx = threadIdx.x; idx < OT_TOK * OT_H; idx += 256)
        sr[idx / OT_H][idx % OT_H] = g_src[(tok0 + idx / OT_H) * HDIM + h0 + idx % OT_H];
    __syncthreads();

    const float2* P2 = reinterpret_cast<const float2*>(
        g_sumP + (size_t)bat * HDIM * HDIM);
    const float2* D2 = reinterpret_cast<const float2*>(delta);

    float a0[OT_TOK], a1[OT_TOK];
#pragma unroll
    for (int t = 0; t < OT_TOK; t++) { a0[t] = 0.f; a1[t] = 0.f; }

#pragma unroll 4
    for (int h = 0; h < OT_H; h++) {
        float2 p = __ldg(&P2[(h0 + h) * 256 + k2]);
        float2 d = __ldg(&D2[(h0 + h) * 256 + k2]);
        float pv0 = fmaf(p.x, 2000.0f, d.x);
        float pv1 = fmaf(p.y, 2000.0f, d.y);
#pragma unroll
        for (int t = 0; t < OT_TOK; t++) {
            float s = sr[t][h];
            a0[t] = fmaf(s, pv0, a0[t]);
            a1[t] = fmaf(s, pv1, a1[t]);
        }
    }
#pragma unroll
    for (int t = 0; t < OT_TOK; t++) {
        atomicAdd(&out[(tok0 + t) * HDIM + 2 * k2],     a0[t]);
        atomicAdd(&out[(tok0 + t) * HDIM + 2 * k2 + 1], a1[t]);
    }
}

// ---------------------------------------------------------------------------
extern "C" void kernel_launch(void* const* d_in, const int* in_sizes, int n_in,
                              void* d_out, int out_size)
{
    const float* X     = (const float*)d_in[0];  // (2,128,768)
    const float* Y     = (const float*)d_in[1];  // (2,128,512)
    const float* W     = (const float*)d_in[2];  // (512,768)
    const float* b     = (const float*)d_in[3];  // (512)
    const float* delta = (const float*)d_in[4];  // (512,512)
    float* out = (float*)d_out;                  // (2,128,512)

    dim3 sgrid(NTOK / BT, HDIM / BH);            // (32, 4) = 128 CTAs
    src_kernel<<<sgrid, 256>>>(X, W, b, out);
    sinkhorn_kernel<<<NTOK, 512>>>(Y);
    dim3 ogrid(NTOK / OT_TOK, HDIM / OT_H);
    out_kernel<<<ogrid, 256>>>(delta, out);
}

// round 16
// speedup vs baseline: 1.1510x; 1.0136x over previous
#include <cuda_runtime.h>

// Problem constants
#define HDIM   512
#define BATCH  2
#define SEQ    128
#define DSRC   768
#define NTOK   (BATCH * SEQ)   // 256
#define NITER  30
#define BSZ    32              // sorted-block size (elements)
#define NBLK   (HDIM / BSZ)    // 16 blocks
#define NPAIR  (BSZ / 2)       // 16 packed pairs per block

// -(SCALE/REG) * log2(e) = -5000 * 1.4426950408889634
#define NEGC  (-7213.4752044448170f)
#define CPOS  (7213.4752044448170f)
// -log2(H)
#define LOGMARG2 (-9.0f)
// cutoff: drop terms with tau < -TW (rel_err empirically invariant 60->24)
#define TW 24.0f

typedef unsigned long long ull;

// Scratch (static device globals; no runtime allocation allowed)
__device__ float g_src[NTOK * HDIM];            // 512 KB
__device__ float g_sumP[BATCH * HDIM * HDIM];   // 2 MB

__device__ __forceinline__ float ex2(float x) {
    float y; asm("ex2.approx.f32 %0, %1;" : "=f"(y) : "f"(x)); return y;
}
__device__ __forceinline__ float lg2(float x) {
    float y; asm("lg2.approx.f32 %0, %1;" : "=f"(y) : "f"(x)); return y;
}
__device__ __forceinline__ ull pack2(float lo, float hi) {
    ull r; asm("mov.b64 %0, {%1, %2};" : "=l"(r) : "f"(lo), "f"(hi)); return r;
}
__device__ __forceinline__ void unpack2(ull v, float& lo, float& hi) {
    asm("mov.b64 {%0, %1}, %2;" : "=f"(lo), "=f"(hi) : "l"(v));
}
__device__ __forceinline__ ull subx2(ull a, ull b) {
    ull r; asm("sub.rn.f32x2 %0, %1, %2;" : "=l"(r) : "l"(a), "l"(b)); return r;
}
__device__ __forceinline__ ull addx2(ull a, ull b) {
    ull r; asm("add.rn.f32x2 %0, %1, %2;" : "=l"(r) : "l"(a), "l"(b)); return r;
}
__device__ __forceinline__ ull mulx2(ull a, ull b) {
    ull r; asm("mul.rn.f32x2 %0, %1, %2;" : "=l"(r) : "l"(a), "l"(b)); return r;
}
__device__ __forceinline__ ull fmax2p(ull a, ull b, ull c) {
    ull r; asm("fma.rn.f32x2 %0, %1, %2, %3;" : "=l"(r) : "l"(a), "l"(b), "l"(c)); return r;
}
// warp-wide f32 max via monotone-uint mapping + int redux (sm_80+)
__device__ __forceinline__ float warp_max_f32(float x) {
    unsigned b = __float_as_uint(x);
    unsigned k = (b & 0x80000000u) ? ~b : (b | 0x80000000u);
    unsigned m;
    asm("redux.sync.max.u32 %0, %1, 0xffffffff;" : "=r"(m) : "r"(k));
    unsigned r = (m & 0x80000000u) ? (m & 0x7fffffffu) : ~m;
    return __uint_as_float(r);
}

#define NZ_P   (BATCH * HDIM * HDIM / 4)   // 131072 float4
#define NZ_OUT (NTOK * HDIM / 4)           // 32768 float4

// ---------------------------------------------------------------------------
// Stage 1: zero scratch+out (graph replays), then tiled GEMM
// src[tok, h] = X[tok] . W[h] + b[h].
// CTA tile: 8 tokens x 128 h, K chunked by 64, 128 threads. Thread owns
// 4 h x 2 tokens: per k one LDS.128 (w) + one broadcast LDS.64 (x pair)
// + 8 FMA -> 2 B smem per FMA (under the 128 B/cyc port; the R15 version
// was 2x OVER it and smem-bound at 42 us).
// ---------------------------------------------------------------------------
#define BT    8      // tokens per CTA tile
#define BH    128    // h per CTA tile
#define KC    64     // k-chunk
#define WPAD  132    // Ws row stride in floats (128 + 4: LDS.128 phase-clean)
#define STH   128    // src threads
__global__ void __launch_bounds__(STH, 2) src_kernel(
    const float* __restrict__ X, const float* __restrict__ W,
    const float* __restrict__ b, float* __restrict__ out)
{
    const int tid = threadIdx.x;
    // zero g_sumP and d_out (harness poisons d_out; out_kernel accumulates)
    {
        float4 z = make_float4(0.f, 0.f, 0.f, 0.f);
        int cta = blockIdx.y * gridDim.x + blockIdx.x;       // 0..127
        int i0 = cta * STH + tid;
        const int stride = 128 * STH;                         // 16384
#pragma unroll
        for (int i = i0; i < NZ_P + NZ_OUT; i += stride) {
            if (i < NZ_P) reinterpret_cast<float4*>(g_sumP)[i] = z;
            else          reinterpret_cast<float4*>(out)[i - NZ_P] = z;
        }
    }

    const int tok0 = blockIdx.x * BT;    // gridDim.x = 32
    const int h0   = blockIdx.y * BH;    // gridDim.y = 4

    __shared__ __align__(16) float Ws[KC * WPAD];   // 33 KB, [kk][h]
    __shared__ __align__(16) float Xs[KC * BT];     // 2 KB, [kk][tok]

    const int hq = (tid & 31) * 4;   // 4-h group within tile (0..124)
    const int tp = tid >> 5;         // token-pair index (0..3)
    const int tA = 2 * tp;           // tokens tA, tA+1

    float a0 = 0.f, a1 = 0.f, a2 = 0.f, a3 = 0.f;   // token tA
    float c0 = 0.f, c1 = 0.f, c2 = 0.f, c3 = 0.f;   // token tA+1

    for (int k0 = 0; k0 < DSRC; k0 += KC) {
        __syncthreads();   // protect previous chunk's reads
        // load X tile: 8 tok x 64 k = 512 floats, 4 per thread
        {
            int idx = tid;
#pragma unroll
            for (int r = 0; r < 4; r++, idx += STH) {
                int tt = idx >> 6;         // token 0..7
                int kk = idx & 63;
                Xs[kk * BT + tt] = X[(tok0 + tt) * DSRC + k0 + kk];
            }
        }
        // load+transpose W tile: thread t -> h = t, full 64-k row (16 float4)
        {
            const float4* wsrc = reinterpret_cast<const float4*>(
                W + (size_t)(h0 + tid) * DSRC + k0);
#pragma unroll
            for (int j = 0; j < 16; j++) {
                float4 w4 = wsrc[j];
                int kk = j * 4;
                Ws[(kk + 0) * WPAD + tid] = w4.x;
                Ws[(kk + 1) * WPAD + tid] = w4.y;
                Ws[(kk + 2) * WPAD + tid] = w4.z;
                Ws[(kk + 3) * WPAD + tid] = w4.w;
            }
        }
        __syncthreads();
        // compute: per kk one LDS.128 (w) + one broadcast LDS.64 (x) + 8 FMA
#pragma unroll 8
        for (int kk = 0; kk < KC; kk++) {
            float4 w = *reinterpret_cast<const float4*>(&Ws[kk * WPAD + hq]);
            float2 x = *reinterpret_cast<const float2*>(&Xs[kk * BT + tA]);
            a0 = fmaf(w.x, x.x, a0);
            a1 = fmaf(w.y, x.x, a1);
            a2 = fmaf(w.z, x.x, a2);
            a3 = fmaf(w.w, x.x, a3);
            c0 = fmaf(w.x, x.y, c0);
            c1 = fmaf(w.y, x.y, c1);
            c2 = fmaf(w.z, x.y, c2);
            c3 = fmaf(w.w, x.y, c3);
        }
    }

    float4 bb = *reinterpret_cast<const float4*>(&b[h0 + hq]);
    float4 rA = make_float4(a0 + bb.x, a1 + bb.y, a2 + bb.z, a3 + bb.w);
    float4 rB = make_float4(c0 + bb.x, c1 + bb.y, c2 + bb.z, c3 + bb.w);
    *reinterpret_cast<float4*>(&g_src[(tok0 + tA) * HDIM + h0 + hq])     = rA;
    *reinterpret_cast<float4*>(&g_src[(tok0 + tA + 1) * HDIM + h0 + hq]) = rB;
}

// ---------------------------------------------------------------------------
// Binary search over a sorted float array (u-init only).
// ---------------------------------------------------------------------------
__device__ __forceinline__ int lboundf(const float* __restrict__ A, float x) {
    int lo = 0, hi = HDIM;
    while (lo < hi) { int m = (lo + hi) >> 1; if (A[m] < x) lo = m + 1; else hi = m; }
    return lo;
}

// ---------------------------------------------------------------------------
// One culled half-pass sum with packed f32x2 math; warp-uniform block votes.
// Q[p] = (x_{2p}, x_{2p+1}, dual_{2p}, dual_{2p+1}) for sorted positions.
// a = sum over qualifying elements of 2^( NEGC*(x - own)^2 + dual + sh ).
// A 32-element block is processed if ANY lane's best-case term >= -TW;
// non-qualifying lanes just add sub-2^-TW mass (strictly more accurate).
// ---------------------------------------------------------------------------
__device__ __forceinline__ float culled_sum(const float4* __restrict__ Q,
                                            const float2* __restrict__ blkRange,
                                            const float* __restrict__ blkMax,
                                            float own, float sh, ull negc2)
{
    const ull own2 = pack2(own, own);
    const ull sh2  = pack2(sh, sh);
    float a0 = 1e-30f, a1 = 0.f;
#pragma unroll 1
    for (int b = 0; b < NBLK; b++) {
        float2 rg = blkRange[b];
        float dd = fmaxf(fmaxf(rg.x - own, own - rg.y), 0.0f);
        bool qual = fmaf(dd * dd, NEGC, blkMax[b] + sh) >= -TW;
        if (__any_sync(0xffffffffu, qual)) {
#pragma unroll
            for (int p = NPAIR * b; p < NPAIR * b + NPAIR; p++) {
                float4 q = Q[p];
                ull X  = pack2(q.x, q.y);
                ull Yd = pack2(q.z, q.w);
                ull d  = subx2(X, own2);
                ull sq = mulx2(d, d);
                ull ys = addx2(Yd, sh2);
                ull e  = fmax2p(sq, negc2, ys);
                float el, eh; unpack2(e, el, eh);
                a0 += ex2(el);
                a1 += ex2(eh);
            }
        }
    }
    return a0 + a1;
}

// ---------------------------------------------------------------------------
// Stage 2: block-culled per-token base-2 log-domain Sinkhorn (fixed 30
// iterations — the reference's result is NOT a converged fixed point).
// s,t bitonic-sorted with index payloads; packed pair arrays for the inner
// loop. Thread tid owns sorted row tid (t side, dual u) and sorted column
// tid (s side, dual v). Warp w == sorted block w; publishes blkMax.
// Half-pass: own_dual -= lg2( culled_sum ) — shifted-LSE update (exact:
// shift = own_dual + 9 keeps all terms <= 0 after each normalization;
// nearest-neighbor u-init guarantees it at iteration 0 too).
// ---------------------------------------------------------------------------
__global__ void __launch_bounds__(512, 2) sinkhorn_kernel(
    const float* __restrict__ Y)
{
    const int tok  = blockIdx.x;
    const int bat  = tok >> 7;
    const int tid  = threadIdx.x;
    const int lane = tid & 31;
    const int warp = tid >> 5;

    __shared__ float sVal[HDIM], tVal[HDIM];      // sorted values
    __shared__ int   sIdx[HDIM], tIdx[HDIM];      // sorted pos -> original
    __shared__ __align__(16) float4 SQ[HDIM / 2]; // (s0,s1,v0,v1) pairs
    __shared__ __align__(16) float4 TQ[HDIM / 2]; // (t0,t1,u0,u1) pairs
    __shared__ float2 rgS[NBLK], rgT[NBLK];       // per-block (lo,hi) values
    __shared__ float blkMaxV[NBLK], blkMaxU[NBLK];

    sVal[tid] = g_src[tok * HDIM + tid];
    tVal[tid] = Y[tok * HDIM + tid];
    sIdx[tid] = tid;
    tIdx[tid] = tid;
    if (tid < NBLK) blkMaxV[tid] = 0.f;
    __syncthreads();

    // joint bitonic sort of s and t (values + index payloads)
    for (int k = 2; k <= HDIM; k <<= 1) {
        for (int j = k >> 1; j > 0; j >>= 1) {
            int ixj = tid ^ j;
            if (ixj > tid) {
                bool up = ((tid & k) == 0);
                float a = sVal[tid], b2 = sVal[ixj];
                if (up ? (a > b2) : (a < b2)) {
                    sVal[tid] = b2; sVal[ixj] = a;
                    int ti = sIdx[tid]; sIdx[tid] = sIdx[ixj]; sIdx[ixj] = ti;
                }
                float c = tVal[tid], d2 = tVal[ixj];
                if (up ? (c > d2) : (c < d2)) {
                    tVal[tid] = d2; tVal[ixj] = c;
                    int ti = tIdx[tid]; tIdx[tid] = tIdx[ixj]; tIdx[ixj] = ti;
                }
            }
            __syncthreads();
        }
    }

    // build packed pair arrays + block ranges
    if (tid < HDIM / 2) {
        SQ[tid] = make_float4(sVal[2 * tid], sVal[2 * tid + 1], 0.f, 0.f);
        TQ[tid] = make_float4(tVal[2 * tid], tVal[2 * tid + 1], 0.f, 0.f);
    }
    if (tid < NBLK) {
        rgS[tid] = make_float2(sVal[BSZ * tid], sVal[BSZ * tid + BSZ - 1]);
        rgT[tid] = make_float2(tVal[BSZ * tid], tVal[BSZ * tid + BSZ - 1]);
    }
    __syncthreads();

    const float t_own = tVal[tid];
    const float s_own = sVal[tid];
    const int   jorig = tIdx[tid];

    // init u via nearest sorted s neighbor: u = -9 + C*d_nn^2
    float u_own;
    {
        int p = lboundf(sVal, t_own);
        float dn = 3.402823466e+38f;
        if (p < HDIM) dn = fabsf(sVal[p] - t_own);
        if (p > 0)    dn = fminf(dn, fabsf(sVal[p - 1] - t_own));
        u_own = LOGMARG2 + CPOS * dn * dn;
    }
    float v_own = 0.f;

    const ull negc2 = pack2(NEGC, NEGC);
    float* SQ_s = reinterpret_cast<float*>(SQ);
    float* TQ_s = reinterpret_cast<float*>(TQ);
    const int own_slot = (tid >> 1) * 4 + 2 + (tid & 1);

    for (int it = 0; it < NITER; it++) {
        // ---- u-pass: culled sum over sorted s blocks ----
        u_own -= lg2(culled_sum(SQ, rgS, blkMaxV, t_own, u_own + 9.0f, negc2));
        TQ_s[own_slot] = u_own;
        {
            float m = warp_max_f32(u_own);
            if (lane == 0) blkMaxU[warp] = m;
        }
        __syncthreads();

        // ---- v-pass: culled sum over sorted t blocks ----
        v_own -= lg2(culled_sum(TQ, rgT, blkMaxU, s_own, v_own + 9.0f, negc2));
        SQ_s[own_slot] = v_own;
        {
            float m = warp_max_f32(v_own);
            if (lane == 0) blkMaxV[warp] = m;
        }
        __syncthreads();
    }

    // ---- Plan: P[jorig, iorig] = 2^(tau - 9), tau = -C d^2 + v + u + 9 ----
    {
        float* rowdst = g_sumP + (size_t)bat * HDIM * HDIM + (size_t)jorig * HDIM;
        const float sh = u_own + 9.0f;
        const ull own2 = pack2(t_own, t_own);
        const ull sh2  = pack2(sh, sh);
#pragma unroll 1
        for (int b = 0; b < NBLK; b++) {
            float2 rg = rgS[b];
            float dd = fmaxf(fmaxf(rg.x - t_own, t_own - rg.y), 0.0f);
            bool qual = fmaf(dd * dd, NEGC, blkMaxV[b] + sh) >= -31.0f;
            if (__any_sync(0xffffffffu, qual)) {
#pragma unroll 4
                for (int p = NPAIR * b; p < NPAIR * b + NPAIR; p++) {
                    float4 q = SQ[p];
                    ull X  = pack2(q.x, q.y);
                    ull Yd = pack2(q.z, q.w);
                    ull d  = subx2(X, own2);
                    ull sq = mulx2(d, d);
                    ull ys = addx2(Yd, sh2);
                    ull e  = fmax2p(sq, negc2, ys);
                    float el, eh; unpack2(e, el, eh);
                    if (el > -31.f) atomicAdd(rowdst + sIdx[2 * p],     ex2(el - 9.0f));
                    if (eh > -31.f) atomicAdd(rowdst + sIdx[2 * p + 1], ex2(eh - 9.0f));
                }
            }
        }
    }
}

// ---------------------------------------------------------------------------
// Stage 3: out[tok, k] += sum_{h in slice} src[tok,h]*(sumP[b,h,k]*2000
//                                                      + delta[h,k])
// Grid (16 token-groups of 16, 16 h-slices of 32). 256 CTAs, 256 threads.
// ---------------------------------------------------------------------------
#define OT_TOK 16
#define OT_H   32
__global__ void __launch_bounds__(256) out_kernel(
    const float* __restrict__ delta, float* __restrict__ out)
{
    const int tok0 = blockIdx.x * OT_TOK;
    const int h0   = blockIdx.y * OT_H;
    const int bat  = tok0 >> 7;       // OT_TOK divides SEQ -> no straddle
    const int k2   = threadIdx.x;     // float2 column index (0..255)

    __shared__ float sr[OT_TOK][OT_H];   // 2 KB
    for (int idx = threadIdx.x; idx < OT_TOK * OT_H; idx += 256)
        sr[idx / OT_H][idx % OT_H] = g_src[(tok0 + idx / OT_H) * HDIM + h0 + idx % OT_H];
    __syncthreads();

    const float2* P2 = reinterpret_cast<const float2*>(
        g_sumP + (size_t)bat * HDIM * HDIM);
    const float2* D2 = reinterpret_cast<const float2*>(delta);

    float a0[OT_TOK], a1[OT_TOK];
#pragma unroll
    for (int t = 0; t < OT_TOK; t++) { a0[t] = 0.f; a1[t] = 0.f; }

#pragma unroll 4
    for (int h = 0; h < OT_H; h++) {
        float2 p = __ldg(&P2[(h0 + h) * 256 + k2]);
        float2 d = __ldg(&D2[(h0 + h) * 256 + k2]);
        float pv0 = fmaf(p.x, 2000.0f, d.x);
        float pv1 = fmaf(p.y, 2000.0f, d.y);
#pragma unroll
        for (int t = 0; t < OT_TOK; t++) {
            float s = sr[t][h];
            a0[t] = fmaf(s, pv0, a0[t]);
            a1[t] = fmaf(s, pv1, a1[t]);
        }
    }
#pragma unroll
    for (int t = 0; t < OT_TOK; t++) {
        atomicAdd(&out[(tok0 + t) * HDIM + 2 * k2],     a0[t]);
        atomicAdd(&out[(tok0 + t) * HDIM + 2 * k2 + 1], a1[t]);
    }
}

// ---------------------------------------------------------------------------
extern "C" void kernel_launch(void* const* d_in, const int* in_sizes, int n_in,
                              void* d_out, int out_size)
{
    const float* X     = (const float*)d_in[0];  // (2,128,768)
    const float* Y     = (const float*)d_in[1];  // (2,128,512)
    const float* W     = (const float*)d_in[2];  // (512,768)
    const float* b     = (const float*)d_in[3];  // (512)
    const float* delta = (const float*)d_in[4];  // (512,512)
    float* out = (float*)d_out;                  // (2,128,512)

    dim3 sgrid(NTOK / BT, HDIM / BH);            // (32, 4) = 128 CTAs
    src_kernel<<<sgrid, STH>>>(X, W, b, out);
    sinkhorn_kernel<<<NTOK, 512>>>(Y);
    dim3 ogrid(NTOK / OT_TOK, HDIM / OT_H);
    out_kernel<<<ogrid, 256>>>(delta, out);
}